// round 3
// baseline (speedup 1.0000x reference)
#include <cuda_runtime.h>

// Analytical reduction of the 4-qubit variational circuit:
//   RZ layers are diagonal phases -> irrelevant to probabilities (params unused).
//   CNOT chain is an XOR-linear basis permutation; with a product initial
//   distribution, <(-1)^{xor subset}> = prod cos(x_j):
//     out = [c1*c2*c3, c0*c1, c0*c1*c2, c0*c1*c2*c3],  c_j = cos(x_j)
//
// R3: latency-bound fix.
//   - __cosf -> MUFU.COS (1 instr, no serial FFMA chain); |x|<~6 is in the
//     accurate range, abs err ~1e-6 << 1e-3 threshold.
//   - 4 front-batched float4 loads per thread (MLP=4, 2KB/warp in flight),
//     1024 blocks = single resident wave, coalesced stride-blockDim access.

#define EPT 4  // float4 elements per thread

__global__ void __launch_bounds__(256)
_VariationalQHead_65481071396152_kernel(
    const float4* __restrict__ x, float4* __restrict__ out, int n)
{
    int base = blockIdx.x * (blockDim.x * EPT) + threadIdx.x;

    float4 v[EPT];
#pragma unroll
    for (int k = 0; k < EPT; k++) {
        int i = base + k * 256;
        if (i < n) v[k] = x[i];
    }

#pragma unroll
    for (int k = 0; k < EPT; k++) {
        int i = base + k * 256;
        if (i < n) {
            float c0 = __cosf(v[k].x);
            float c1 = __cosf(v[k].y);
            float c2 = __cosf(v[k].z);
            float c3 = __cosf(v[k].w);
            float c01  = c0 * c1;
            float c012 = c01 * c2;
            float4 o;
            o.x = c1 * c2 * c3;
            o.y = c01;
            o.z = c012;
            o.w = c012 * c3;
            out[i] = o;
        }
    }
}

extern "C" void kernel_launch(void* const* d_in, const int* in_sizes, int n_in,
                              void* d_out, int out_size)
{
    const float4* x = (const float4*)d_in[0];   // x: [B,4] float32, contiguous
    float4* out = (float4*)d_out;               // out: [B,4] float32
    int n = in_sizes[0] / 4;                    // batch count (float4 elems)
    int block = 256;
    int grid = (n + block * EPT - 1) / (block * EPT);
    _VariationalQHead_65481071396152_kernel<<<grid, block>>>(x, out, n);
}